// round 1
// baseline (speedup 1.0000x reference)
#include <cuda_runtime.h>
#include <math.h>

// Problem dims
#define NB 1024
#define ND 64
#define NH 512

// ---------------- scratch (__device__ globals; no allocation) ----------------
__device__ __align__(256) float g_A  [NH*NH];   // A[k,l] = W2[k,l]*C[l,k]
__device__ __align__(256) float g_AT [NH*NH];   // A^T
__device__ __align__(256) float g_W2T[NH*NH];
__device__ __align__(256) float g_W3T[ND*NH];   // W3T[j,l] = W3[l,j]
__device__ __align__(256) float g_W1T[NH*ND];   // W1T[k,i] = W1[i,k]
__device__ __align__(256) float g_w3s[NH];      // row-sums of W3
__device__ __align__(256) float g_h1 [NB*NH];
__device__ __align__(256) float g_h2 [NB*NH];
__device__ __align__(256) float g_d2 [NB*NH];
__device__ __align__(256) float g_U  [NB*NH];
__device__ __align__(256) float g_V  [NB*NH];
__device__ __align__(256) float g_P  [NB*NH];
__device__ __align__(256) float g_wb [NB*NH];
__device__ __align__(256) float g_c  [NB*NH];
__device__ __align__(256) float g_s  [NB*ND];
__device__ __align__(256) float g_y  [NB*ND];
__device__ __align__(256) float g_st [NB];

// ---------------- prep: A, A^T, W2^T, W3^T, W1^T, w3sum ----------------
__global__ void prep_kernel(const float* __restrict__ W1,
                            const float* __restrict__ W2,
                            const float* __restrict__ W3) {
    int k = blockIdx.x * 16 + threadIdx.x;   // 0..511
    int l = blockIdx.y * 16 + threadIdx.y;   // 0..511
    float c = 0.f;
#pragma unroll
    for (int i = 0; i < ND; i++) c += W3[l*ND + i] * W1[i*NH + k];
    float w2 = W2[k*NH + l];
    float a  = w2 * c;
    g_A [k*NH + l] = a;
    g_AT[l*NH + k] = a;
    g_W2T[l*NH + k] = w2;
    if (l < ND) g_W1T[k*ND + l] = W1[l*NH + k];
    if (k < ND) g_W3T[k*NH + l] = W3[l*ND + k];
    if (k == 0 && blockIdx.x == 0) {
        float ssum = 0.f;
#pragma unroll
        for (int j = 0; j < ND; j++) ssum += W3[l*ND + j];
        g_w3s[l] = ssum;
    }
}

// ---------------- generic tiled GEMM (64x64 tile, BK=16, 256 thr, 4x4/thr) ----
enum { M_L1 = 0, M_Z2V2 = 1, M_S = 2, M_P = 3, M_V = 4, M_U = 5, M_QW = 6, M_LOSS = 7 };

template<int MODE, int KDIM, int LDA, int LDB>
__global__ void __launch_bounds__(256)
gemm_k(const float* __restrict__ pA,   // harness ptrs as needed per mode
       const float* __restrict__ pB,
       const float* __restrict__ pC,
       const float* __restrict__ pD,
       float* __restrict__ pOut) {
    constexpr int BK = 16;
    __shared__ __align__(16) float Xs [BK][68];
    __shared__ __align__(16) float Bs [BK][68];
    __shared__ __align__(16) float Xs2[BK][68];   // only used by M_Z2V2

    const float* Xg =
        (MODE == M_L1)   ? pA   :
        (MODE == M_Z2V2) ? g_h1 :
        (MODE == M_S)    ? g_h2 :
        (MODE == M_P)    ? g_y  :
        (MODE == M_V)    ? g_h1 :
        (MODE == M_U)    ? g_h2 :
        (MODE == M_QW)   ? g_wb : g_c;
    const float* Bg =
        (MODE == M_L1 || MODE == M_Z2V2 || MODE == M_S) ? pB :
        (MODE == M_P)  ? g_W3T :
        (MODE == M_V)  ? g_A   :
        (MODE == M_U)  ? g_AT  :
        (MODE == M_QW) ? g_W2T : g_W1T;
    float* out0 =
        (MODE == M_L1)   ? g_h1 :
        (MODE == M_Z2V2) ? g_h2 :
        (MODE == M_S)    ? g_s  :
        (MODE == M_P)    ? g_P  :
        (MODE == M_V)    ? g_V  :
        (MODE == M_U)    ? g_U  :
        (MODE == M_QW)   ? g_c  : pOut;

    const int tid = threadIdx.x;
    const int tx = tid & 15, ty = tid >> 4;
    const int m0 = blockIdx.y * 64;
    const int n0 = blockIdx.x * 64;

    float acc [4][4] = {};
    float acc2[4][4] = {};

    const int lrow = tid >> 2;          // 0..63  (X tile row = batch)
    const int lkq  = (tid & 3) * 4;     // 0,4,8,12
    const int brow = tid >> 4;          // 0..15  (B tile row = k)
    const int bnq  = (tid & 15) * 4;    // 0..60

    for (int k0 = 0; k0 < KDIM; k0 += BK) {
        // ---- X tile (stored k-major / transposed for vector reads) ----
        if (MODE == M_L1) {
#pragma unroll
            for (int j = 0; j < 4; j++) {
                int k = k0 + lkq + j;
                float v = 0.f;
                if (k < ND)       v = pA[(m0 + lrow) * ND + k];   // x
                else if (k == ND) v = pD[m0 + lrow];              // t
                Xs[lkq + j][lrow] = v;
            }
        } else {
            float4 v = *(const float4*)(Xg + (size_t)(m0 + lrow) * LDA + k0 + lkq);
            float vv[4] = {v.x, v.y, v.z, v.w};
#pragma unroll
            for (int j = 0; j < 4; j++) {
                float xv = vv[j];
                if (MODE == M_U || MODE == M_V) xv = 1.f - xv * xv;  // a = 1-h^2
                Xs[lkq + j][lrow] = xv;
                if (MODE == M_Z2V2)   // d1 = (1-h1^2) * w1t[k]
                    Xs2[lkq + j][lrow] = (1.f - vv[j]*vv[j]) * pD[k0 + lkq + j];
            }
        }
        // ---- B tile ----
        {
            int k = k0 + brow;
            float4 v;
            if ((KDIM % BK != 0) && k >= KDIM) v = make_float4(0.f,0.f,0.f,0.f);
            else v = *(const float4*)(Bg + (size_t)k * LDB + n0 + bnq);
            *(float4*)&Bs[brow][bnq] = v;
        }
        __syncthreads();
#pragma unroll
        for (int kk = 0; kk < BK; kk++) {
            float4 av = *(const float4*)&Xs[kk][ty*4];
            float4 bv = *(const float4*)&Bs[kk][tx*4];
            float ar[4] = {av.x, av.y, av.z, av.w};
            float br[4] = {bv.x, bv.y, bv.z, bv.w};
#pragma unroll
            for (int r = 0; r < 4; r++)
#pragma unroll
                for (int c = 0; c < 4; c++)
                    acc[r][c] += ar[r] * br[c];
            if (MODE == M_Z2V2) {
                float4 a2v = *(const float4*)&Xs2[kk][ty*4];
                float a2r[4] = {a2v.x, a2v.y, a2v.z, a2v.w};
#pragma unroll
                for (int r = 0; r < 4; r++)
#pragma unroll
                    for (int c = 0; c < 4; c++)
                        acc2[r][c] += a2r[r] * br[c];
            }
        }
        __syncthreads();
    }

    // ---- epilogues ----
    const int mrow = m0 + ty * 4;
    const int ncol = n0 + tx * 4;

    if (MODE == M_L1) {
#pragma unroll
        for (int r = 0; r < 4; r++)
#pragma unroll
            for (int c = 0; c < 4; c++)
                out0[(size_t)(mrow + r)*NH + ncol + c] = tanhf(acc[r][c] + pC[ncol + c]);
    } else if (MODE == M_Z2V2) {
#pragma unroll
        for (int r = 0; r < 4; r++)
#pragma unroll
            for (int c = 0; c < 4; c++) {
                size_t idx = (size_t)(mrow + r)*NH + ncol + c;
                float h2 = tanhf(acc[r][c] + pC[ncol + c]);
                out0[idx] = h2;
                g_d2[idx] = (1.f - h2*h2) * acc2[r][c];
            }
    } else if (MODE == M_S) {
#pragma unroll
        for (int r = 0; r < 4; r++)
#pragma unroll
            for (int c = 0; c < 4; c++) {
                size_t idx = (size_t)(mrow + r)*ND + ncol + c;
                float sv = acc[r][c] + pC[ncol + c];
                out0[idx] = sv;
                g_y [idx] = 2.f * sv + pD[idx];   // y = 2s + x
            }
    } else if (MODE == M_P || MODE == M_V || MODE == M_U) {
#pragma unroll
        for (int r = 0; r < 4; r++)
#pragma unroll
            for (int c = 0; c < 4; c++)
                out0[(size_t)(mrow + r)*NH + ncol + c] = acc[r][c];
    } else if (MODE == M_QW) {
#pragma unroll
        for (int r = 0; r < 4; r++)
#pragma unroll
            for (int c = 0; c < 4; c++) {
                size_t idx = (size_t)(mrow + r)*NH + ncol + c;
                float h1 = g_h1[idx];
                float a1 = 1.f - h1*h1;
                out0[idx] = a1 * acc[r][c] - 2.f * h1 * a1 * g_U[idx];  // c_k
            }
    } else if (MODE == M_LOSS) {
        __shared__ float red[64][17];
        float ps[4] = {0.f, 0.f, 0.f, 0.f};
#pragma unroll
        for (int r = 0; r < 4; r++) {
            float stv  = g_st[mrow + r];
            float bet  = pC[mrow + r];
#pragma unroll
            for (int c = 0; c < 4; c++) {
                float g = acc[r][c] + g_s[(size_t)(mrow + r)*ND + ncol + c];
                ps[r] += fabsf(stv - 0.5f * bet * g);
            }
        }
#pragma unroll
        for (int r = 0; r < 4; r++) red[ty*4 + r][tx] = ps[r];
        __syncthreads();
        if (tid < 64) {
            float tsum = 0.f;
#pragma unroll
            for (int i = 0; i < 16; i++) tsum += red[tid][i];
            out0[m0 + tid] = tsum * (1.f / 64.f);
        }
    }
}

// ---------------- s_t = d2 . w3sum (one warp / row, deterministic order) -----
__global__ void st_kernel() {
    int b = blockIdx.x * (blockDim.x >> 5) + (threadIdx.x >> 5);
    int lane = threadIdx.x & 31;
    float s = 0.f;
    for (int l = lane; l < NH; l += 32) s += g_d2[(size_t)b*NH + l] * g_w3s[l];
#pragma unroll
    for (int o = 16; o; o >>= 1) s += __shfl_down_sync(0xffffffffu, s, o);
    if (lane == 0) g_st[b] = s;
}

// ---------------- w = a2 * (P - 2 h2 V) -------------------------------------
__global__ void wb_kernel() {
    int i = blockIdx.x * blockDim.x + threadIdx.x;
    float h2 = g_h2[i];
    g_wb[i] = (1.f - h2*h2) * (g_P[i] - 2.f * h2 * g_V[i]);
}

// ---------------- launch -----------------------------------------------------
extern "C" void kernel_launch(void* const* d_in, const int* in_sizes, int n_in,
                              void* d_out, int out_size) {
    const float* x    = (const float*)d_in[0];
    const float* t    = (const float*)d_in[1];
    const float* beta = (const float*)d_in[2];
    const float* W1   = (const float*)d_in[3];
    const float* b1   = (const float*)d_in[4];
    const float* W2   = (const float*)d_in[5];
    const float* b2   = (const float*)d_in[6];
    const float* W3   = (const float*)d_in[7];
    const float* b3   = (const float*)d_in[8];
    float* out = (float*)d_out;
    const float* w1t = W1 + (size_t)ND * NH;   // W1[64, :] (the t-row)

    dim3 gHH(NH/64, NB/64);   // (8,16)
    dim3 gD (1,     NB/64);   // (1,16)

    prep_kernel<<<dim3(NH/16, NH/16), dim3(16,16)>>>(W1, W2, W3);
    // h1 = tanh([x,t] @ W1 + b1)
    gemm_k<M_L1,   65, 64, NH><<<gHH, 256>>>(x, W1, b1, t, nullptr);
    // h2 = tanh(h1 @ W2 + b2);  d2 = (1-h2^2) * (d1 @ W2)
    gemm_k<M_Z2V2, NH, NH, NH><<<gHH, 256>>>(nullptr, W2, b2, w1t, nullptr);
    // s_t[b]
    st_kernel<<<NB/8, 256>>>();
    // s = h2 @ W3 + b3;  y = 2s + x
    gemm_k<M_S,    NH, NH, ND><<<gD, 256>>>(nullptr, W3, b3, x, nullptr);
    // P = y @ W3^T
    gemm_k<M_P,    ND, ND, NH><<<gHH, 256>>>(nullptr, nullptr, nullptr, nullptr, nullptr);
    // V = a1 @ A
    gemm_k<M_V,    NH, NH, NH><<<gHH, 256>>>(nullptr, nullptr, nullptr, nullptr, nullptr);
    // w = a2 * (P - 2 h2 V)
    wb_kernel<<<(NB*NH)/256, 256>>>();
    // U = a2 @ A^T
    gemm_k<M_U,    NH, NH, NH><<<gHH, 256>>>(nullptr, nullptr, nullptr, nullptr, nullptr);
    // c = a1*(w @ W2^T) - 2 h1 a1 U
    gemm_k<M_QW,   NH, NH, NH><<<gHH, 256>>>(nullptr, nullptr, nullptr, nullptr, nullptr);
    // G = c @ W1x^T + s;  loss = mean |s_t - 0.5 beta G|
    gemm_k<M_LOSS, NH, NH, ND><<<gD, 256>>>(nullptr, nullptr, beta, nullptr, out);
}

// round 2
// speedup vs baseline: 1.3415x; 1.3415x over previous
#include <cuda_runtime.h>
#include <math.h>

#define NB 1024
#define ND 64
#define NH 512

// ---------------- scratch (__device__ globals; no allocation) ----------------
__device__ __align__(256) float g_A  [NH*NH];   // A[k,l] = W2[k,l]*C[l,k]
__device__ __align__(256) float g_AT [NH*NH];
__device__ __align__(256) float g_W2T[NH*NH];
__device__ __align__(256) float g_W3T[ND*NH];
__device__ __align__(256) float g_W1T[NH*ND];
__device__ __align__(256) float g_w3s[NH];
__device__ __align__(256) float g_h1 [NB*NH];
__device__ __align__(256) float g_h2 [NB*NH];
__device__ __align__(256) float g_U  [NB*NH];
__device__ __align__(256) float g_V  [NB*NH];
__device__ __align__(256) float g_wb [NB*NH];
__device__ __align__(256) float g_c  [NB*NH];
__device__ __align__(256) float g_s  [NB*ND];
__device__ __align__(256) float g_y  [NB*ND];
__device__ __align__(256) float g_st [NB];
__device__ __align__(256) float g_stp[NB*8];    // per-(row, n-block) partials of s_t

// ---------------- prep: A, A^T, W2^T, W3^T, W1^T, w3sum ----------------
__global__ void prep_kernel(const float* __restrict__ W1,
                            const float* __restrict__ W2,
                            const float* __restrict__ W3) {
    int k = blockIdx.x * 16 + threadIdx.x;
    int l = blockIdx.y * 16 + threadIdx.y;
    float c = 0.f;
#pragma unroll
    for (int i = 0; i < ND; i++) c += W3[l*ND + i] * W1[i*NH + k];
    float w2 = W2[k*NH + l];
    float a  = w2 * c;
    g_A [k*NH + l] = a;
    g_AT[l*NH + k] = a;
    g_W2T[l*NH + k] = w2;
    if (l < ND) g_W1T[k*ND + l] = W1[l*NH + k];
    if (k < ND) g_W3T[k*NH + l] = W3[l*ND + k];
    if (k == 0 && blockIdx.x == 0) {
        float ssum = 0.f;
#pragma unroll
        for (int j = 0; j < ND; j++) ssum += W3[l*ND + j];
        g_w3s[l] = ssum;
    }
}

// ---------------- fused GEMM family -----------------------------------------
enum { M_L1 = 0, M_Z2V2 = 1, M_S = 2, M_P = 3, M_VU = 4, M_QW = 5, M_LOSS = 6 };

template<int MODE, int KDIM, int LDA, int LDB>
__global__ void __launch_bounds__(256)
gemm_k(const float* __restrict__ pA, const float* __restrict__ pB,
       const float* __restrict__ pC, const float* __restrict__ pD,
       float* __restrict__ pOut) {
    constexpr int BK = 32;
    constexpr bool THIN = (MODE == M_S || MODE == M_LOSS);

    if constexpr (THIN) {
        // ---- 16x64 tile, 256 threads, 1x4 per thread ----
        __shared__ __align__(16) float Xs[BK][17];
        __shared__ __align__(16) float Bs[BK][68];
        const int tid = threadIdx.x;
        const int tx = tid & 15, ty = tid >> 4;
        const int m0 = blockIdx.y * 16;

        const float* Xg = (MODE == M_S) ? g_h2 : g_c;
        const float* Bg = (MODE == M_S) ? pB   : g_W1T;

        if constexpr (MODE == M_S) {     // finalize s_t for this block's rows
            if (tid < 16) {
                float s = 0.f;
#pragma unroll
                for (int j = 0; j < 8; j++) s += g_stp[(m0 + tid) * 8 + j];
                g_st[m0 + tid] = s;
            }
        }

        float acc[4] = {0.f, 0.f, 0.f, 0.f};
        for (int k0 = 0; k0 < KDIM; k0 += BK) {
            {   int row = tid >> 4;
                int kc  = (tid & 15) * 2;
                float2 v = *(const float2*)(Xg + (size_t)(m0 + row) * LDA + k0 + kc);
                Xs[kc][row] = v.x; Xs[kc + 1][row] = v.y;
            }
            {   int brow = tid >> 4, bnq = (tid & 15) * 4;
                *(float4*)&Bs[brow][bnq] =
                    *(const float4*)(Bg + (size_t)(k0 + brow) * LDB + bnq);
                *(float4*)&Bs[brow + 16][bnq] =
                    *(const float4*)(Bg + (size_t)(k0 + brow + 16) * LDB + bnq);
            }
            __syncthreads();
#pragma unroll
            for (int kk = 0; kk < BK; kk++) {
                float a = Xs[kk][ty];
                float4 b = *(const float4*)&Bs[kk][tx * 4];
                acc[0] += a * b.x; acc[1] += a * b.y;
                acc[2] += a * b.z; acc[3] += a * b.w;
            }
            __syncthreads();
        }

        const int row = m0 + ty, col = tx * 4;
        if constexpr (MODE == M_S) {
#pragma unroll
            for (int c = 0; c < 4; c++) {
                size_t idx = (size_t)row * ND + col + c;
                float sv = acc[c] + pC[col + c];
                g_s[idx] = sv;
                g_y[idx] = 2.f * sv + pD[idx];     // y = 2s + x
            }
        } else {  // M_LOSS
            float stv = g_st[row], bet = pC[row];
            float ps = 0.f;
#pragma unroll
            for (int c = 0; c < 4; c++) {
                float g = acc[c] + g_s[(size_t)row * ND + col + c];
                ps += fabsf(stv - 0.5f * bet * g);
            }
#pragma unroll
            for (int o = 8; o; o >>= 1) ps += __shfl_xor_sync(0xffffffffu, ps, o);
            if (tx == 0) pOut[row] = ps * (1.f / 64.f);
        }
        return;
    } else {
        // ---- 64x64 tile, 256 threads, 4x4 per thread, BK=32 ----
        constexpr bool DUAL = (MODE == M_Z2V2 || MODE == M_VU);
        __shared__ __align__(16) float Xs [BK][68];
        __shared__ __align__(16) float Bs [BK][68];
        __shared__ __align__(16) float Xs2[DUAL ? BK : 1][68];
        __shared__ __align__(16) float Bs2[(MODE == M_VU) ? BK : 1][68];

        const int tid = threadIdx.x;
        const int tx = tid & 15, ty = tid >> 4;
        const int m0 = blockIdx.y * 64;
        const int n0 = blockIdx.x * 64;

        const float* Xg =
            (MODE == M_Z2V2) ? g_h1 :
            (MODE == M_P)    ? g_y  :
            (MODE == M_QW)   ? g_wb : g_h1;  // M_VU handled specially
        const float* Bg =
            (MODE == M_L1 || MODE == M_Z2V2) ? pB :
            (MODE == M_P)  ? g_W3T :
            (MODE == M_VU) ? g_A   : g_W2T;

        float acc [4][4] = {};
        float acc2[4][4] = {};

        const int lrow = tid >> 2;
        const int lkq  = (tid & 3) * 4;
        const int brow = tid >> 4;
        const int bnq  = (tid & 15) * 4;

        for (int k0 = 0; k0 < KDIM; k0 += BK) {
            // ---- X tiles ----
#pragma unroll
            for (int half = 0; half < 2; half++) {
                const int kq = lkq + half * 16;
                if constexpr (MODE == M_L1) {
#pragma unroll
                    for (int j = 0; j < 4; j++) {
                        int k = k0 + kq + j;
                        float v = 0.f;
                        if (k < ND)       v = pA[(m0 + lrow) * ND + k];
                        else if (k == ND) v = pD[m0 + lrow];
                        Xs[kq + j][lrow] = v;
                    }
                } else if constexpr (MODE == M_VU) {
                    size_t off = (size_t)(m0 + lrow) * NH + k0 + kq;
                    float4 v1 = *(const float4*)(g_h1 + off);
                    float4 v2 = *(const float4*)(g_h2 + off);
                    float a1[4] = {v1.x, v1.y, v1.z, v1.w};
                    float a2[4] = {v2.x, v2.y, v2.z, v2.w};
#pragma unroll
                    for (int j = 0; j < 4; j++) {
                        Xs [kq + j][lrow] = 1.f - a1[j] * a1[j];
                        Xs2[kq + j][lrow] = 1.f - a2[j] * a2[j];
                    }
                } else {
                    float4 v = *(const float4*)(Xg + (size_t)(m0 + lrow) * LDA + k0 + kq);
                    float vv[4] = {v.x, v.y, v.z, v.w};
#pragma unroll
                    for (int j = 0; j < 4; j++) {
                        Xs[kq + j][lrow] = vv[j];
                        if constexpr (MODE == M_Z2V2)
                            Xs2[kq + j][lrow] = (1.f - vv[j] * vv[j]) * pD[k0 + kq + j];
                    }
                }
            }
            // ---- B tiles ----
#pragma unroll
            for (int half = 0; half < 2; half++) {
                int k = k0 + brow + half * 16;
                float4 v;
                if ((KDIM % BK != 0) && k >= KDIM) v = make_float4(0.f, 0.f, 0.f, 0.f);
                else v = *(const float4*)(Bg + (size_t)k * LDB + n0 + bnq);
                *(float4*)&Bs[brow + half * 16][bnq] = v;
                if constexpr (MODE == M_VU) {
                    float4 v2 = *(const float4*)(g_AT + (size_t)k * NH + n0 + bnq);
                    *(float4*)&Bs2[brow + half * 16][bnq] = v2;
                }
            }
            __syncthreads();
#pragma unroll
            for (int kk = 0; kk < BK; kk++) {
                float4 av = *(const float4*)&Xs[kk][ty * 4];
                float4 bv = *(const float4*)&Bs[kk][tx * 4];
                float ar[4] = {av.x, av.y, av.z, av.w};
                float br[4] = {bv.x, bv.y, bv.z, bv.w};
#pragma unroll
                for (int r = 0; r < 4; r++)
#pragma unroll
                    for (int c = 0; c < 4; c++)
                        acc[r][c] += ar[r] * br[c];
                if constexpr (MODE == M_Z2V2) {
                    float4 a2v = *(const float4*)&Xs2[kk][ty * 4];
                    float a2r[4] = {a2v.x, a2v.y, a2v.z, a2v.w};
#pragma unroll
                    for (int r = 0; r < 4; r++)
#pragma unroll
                        for (int c = 0; c < 4; c++)
                            acc2[r][c] += a2r[r] * br[c];
                } else if constexpr (MODE == M_VU) {
                    float4 a2v = *(const float4*)&Xs2[kk][ty * 4];
                    float4 b2v = *(const float4*)&Bs2[kk][tx * 4];
                    float a2r[4] = {a2v.x, a2v.y, a2v.z, a2v.w};
                    float b2r[4] = {b2v.x, b2v.y, b2v.z, b2v.w};
#pragma unroll
                    for (int r = 0; r < 4; r++)
#pragma unroll
                        for (int c = 0; c < 4; c++)
                            acc2[r][c] += a2r[r] * b2r[c];
                }
            }
            __syncthreads();
        }

        // ---- epilogues ----
        const int mrow = m0 + ty * 4;
        const int ncol = n0 + tx * 4;

        if constexpr (MODE == M_L1) {
#pragma unroll
            for (int r = 0; r < 4; r++)
#pragma unroll
                for (int c = 0; c < 4; c++)
                    g_h1[(size_t)(mrow + r) * NH + ncol + c] =
                        tanhf(acc[r][c] + pC[ncol + c]);
        } else if constexpr (MODE == M_Z2V2) {
            float ps[4] = {0.f, 0.f, 0.f, 0.f};
#pragma unroll
            for (int r = 0; r < 4; r++)
#pragma unroll
                for (int c = 0; c < 4; c++) {
                    size_t idx = (size_t)(mrow + r) * NH + ncol + c;
                    float h2 = tanhf(acc[r][c] + pC[ncol + c]);
                    g_h2[idx] = h2;
                    float d2 = (1.f - h2 * h2) * acc2[r][c];
                    ps[r] += d2 * g_w3s[ncol + c];
                }
            // per-block partial of s_t (deterministic reduce)
            float* red = &Xs[0][0];       // reuse smem (safe: after final sync)
#pragma unroll
            for (int r = 0; r < 4; r++) red[(ty * 4 + r) * 17 + tx] = ps[r];
            __syncthreads();
            if (tid < 64) {
                float tsum = 0.f;
#pragma unroll
                for (int i = 0; i < 16; i++) tsum += red[tid * 17 + i];
                g_stp[(size_t)(m0 + tid) * 8 + blockIdx.x] = tsum;
            }
        } else if constexpr (MODE == M_VU) {
#pragma unroll
            for (int r = 0; r < 4; r++)
#pragma unroll
                for (int c = 0; c < 4; c++) {
                    size_t idx = (size_t)(mrow + r) * NH + ncol + c;
                    g_V[idx] = acc[r][c];
                    g_U[idx] = acc2[r][c];
                }
        } else if constexpr (MODE == M_P) {
#pragma unroll
            for (int r = 0; r < 4; r++)
#pragma unroll
                for (int c = 0; c < 4; c++) {
                    size_t idx = (size_t)(mrow + r) * NH + ncol + c;
                    float h2 = g_h2[idx];
                    g_wb[idx] = (1.f - h2 * h2) * (acc[r][c] - 2.f * h2 * g_V[idx]);
                }
        } else if constexpr (MODE == M_QW) {
#pragma unroll
            for (int r = 0; r < 4; r++)
#pragma unroll
                for (int c = 0; c < 4; c++) {
                    size_t idx = (size_t)(mrow + r) * NH + ncol + c;
                    float h1 = g_h1[idx];
                    float a1 = 1.f - h1 * h1;
                    g_c[idx] = a1 * acc[r][c] - 2.f * h1 * a1 * g_U[idx];
                }
        }
    }
}

// ---------------- launch -----------------------------------------------------
extern "C" void kernel_launch(void* const* d_in, const int* in_sizes, int n_in,
                              void* d_out, int out_size) {
    const float* x    = (const float*)d_in[0];
    const float* t    = (const float*)d_in[1];
    const float* beta = (const float*)d_in[2];
    const float* W1   = (const float*)d_in[3];
    const float* b1   = (const float*)d_in[4];
    const float* W2   = (const float*)d_in[5];
    const float* b2   = (const float*)d_in[6];
    const float* W3   = (const float*)d_in[7];
    const float* b3   = (const float*)d_in[8];
    float* out = (float*)d_out;
    const float* w1t = W1 + (size_t)ND * NH;   // W1 row 64 (the t-row)

    dim3 gHH(NH/64, NB/64);    // (8,16) = 128 blocks
    dim3 gThin(1, NB/16);      // (1,64) = 64 blocks

    prep_kernel<<<dim3(NH/16, NH/16), dim3(16,16)>>>(W1, W2, W3);
    // h1 = tanh([x,t] @ W1 + b1)
    gemm_k<M_L1,   65, 64, NH><<<gHH, 256>>>(x, W1, b1, t, nullptr);
    // h2 = tanh(h1 @ W2 + b2);  s_t partials from d2 = (1-h2^2)*(d1 @ W2)
    gemm_k<M_Z2V2, NH, NH, NH><<<gHH, 256>>>(nullptr, W2, b2, w1t, nullptr);
    // V = a1 @ A;  U = a2 @ A^T (dual)
    gemm_k<M_VU,   NH, NH, NH><<<gHH, 256>>>(nullptr, nullptr, nullptr, nullptr, nullptr);
    // s = h2 @ W3 + b3;  y = 2s + x;  finalize s_t
    gemm_k<M_S,    NH, NH, ND><<<gThin, 256>>>(nullptr, W3, b3, x, nullptr);
    // P = y @ W3^T;  fused wb = a2 * (P - 2 h2 V)
    gemm_k<M_P,    ND, ND, NH><<<gHH, 256>>>(nullptr, nullptr, nullptr, nullptr, nullptr);
    // c = a1*(wb @ W2^T) - 2 h1 a1 U
    gemm_k<M_QW,   NH, NH, NH><<<gHH, 256>>>(nullptr, nullptr, nullptr, nullptr, nullptr);
    // G = c @ W1x^T + s;  loss = mean |s_t - 0.5 beta G|
    gemm_k<M_LOSS, NH, NH, ND><<<gThin, 256>>>(nullptr, nullptr, beta, nullptr, out);
}

// round 4
// speedup vs baseline: 1.5892x; 1.1846x over previous
#include <cuda_runtime.h>
#include <cuda_bf16.h>
#include <math.h>
#include <stdint.h>

#define NB 1024
#define ND 64
#define NH 512

// ---------------- scratch ----------------------------------------------------
__device__ __align__(256) float g_A  [NH*NH];   // A[k,l] = W2[k,l]*C[l,k]
__device__ __align__(256) float g_AT [NH*NH];
__device__ __align__(256) float g_W2T[NH*NH];
__device__ __align__(256) float g_W3T[ND*NH];
__device__ __align__(256) float g_W1T[NH*ND];
__device__ __align__(256) float g_w3s[NH];
__device__ __align__(256) float g_h1 [NB*NH];
__device__ __align__(256) float g_h2 [NB*NH];
__device__ __align__(256) float g_U  [NB*NH];
__device__ __align__(256) float g_V  [NB*NH];
__device__ __align__(256) float g_wb [NB*NH];
__device__ __align__(256) float g_r1 [NB*NH];   // h2raw, later qw_raw
__device__ __align__(256) float g_r2 [NB*NH];   // z2
__device__ __align__(256) float g_s  [NB*ND];
__device__ __align__(256) float g_y  [NB*ND];
__device__ __align__(256) float g_st [NB];

// ---------------- helpers ------------------------------------------------
__device__ __forceinline__ uint32_t smem_u32(const void* p) {
    return (uint32_t)__cvta_generic_to_shared(p);
}
__device__ __forceinline__ void sts_v2(uint32_t addr, uint32_t a, uint32_t b) {
    asm volatile("st.shared.v2.b32 [%0], {%1,%2};" :: "r"(addr), "r"(a), "r"(b));
}
__device__ __forceinline__ void split2(float x0, float x1, uint32_t& hi, uint32_t& lo) {
    __nv_bfloat16 h0 = __float2bfloat16(x0), h1 = __float2bfloat16(x1);
    __nv_bfloat16 l0 = __float2bfloat16(x0 - __bfloat162float(h0));
    __nv_bfloat16 l1 = __float2bfloat16(x1 - __bfloat162float(h1));
    __nv_bfloat162 H; H.x = h0; H.y = h1;
    __nv_bfloat162 L; L.x = l0; L.y = l1;
    hi = *reinterpret_cast<uint32_t*>(&H);
    lo = *reinterpret_cast<uint32_t*>(&L);
}
__device__ __forceinline__ void ldsm_x4(uint32_t* r, uint32_t addr) {
    asm volatile("ldmatrix.sync.aligned.m8n8.x4.shared.b16 {%0,%1,%2,%3}, [%4];"
                 : "=r"(r[0]), "=r"(r[1]), "=r"(r[2]), "=r"(r[3]) : "r"(addr));
}
__device__ __forceinline__ void ldsm_x2(uint32_t* r, uint32_t addr) {
    asm volatile("ldmatrix.sync.aligned.m8n8.x2.shared.b16 {%0,%1}, [%2];"
                 : "=r"(r[0]), "=r"(r[1]) : "r"(addr));
}
__device__ __forceinline__ void mma16816(float* c, const uint32_t* a, const uint32_t* b) {
    asm volatile(
        "mma.sync.aligned.m16n8k16.row.col.f32.bf16.bf16.f32 "
        "{%0,%1,%2,%3}, {%4,%5,%6,%7}, {%8,%9}, {%0,%1,%2,%3};"
        : "+f"(c[0]), "+f"(c[1]), "+f"(c[2]), "+f"(c[3])
        : "r"(a[0]), "r"(a[1]), "r"(a[2]), "r"(a[3]), "r"(b[0]), "r"(b[1]));
}
__device__ __forceinline__ uint32_t sw128(uint32_t byte) {
    return byte ^ ((byte >> 3) & 0x70);
}

// ---------------- prep -------------------------------------------------------
__global__ void prep_kernel(const float* __restrict__ W1,
                            const float* __restrict__ W2,
                            const float* __restrict__ W3) {
    int k = blockIdx.x * 16 + threadIdx.x;
    int l = blockIdx.y * 16 + threadIdx.y;
    float c = 0.f;
#pragma unroll
    for (int i = 0; i < ND; i++) c += W3[l*ND + i] * W1[i*NH + k];
    float w2 = W2[k*NH + l];
    float a  = w2 * c;
    g_A [k*NH + l] = a;
    g_AT[l*NH + k] = a;
    g_W2T[l*NH + k] = w2;
    if (l < ND) g_W1T[k*ND + l] = W1[l*NH + k];
    if (k < ND) g_W3T[k*NH + l] = W3[l*ND + k];
    if (k == 0 && blockIdx.x == 0) {
        float ssum = 0.f;
#pragma unroll
        for (int j = 0; j < ND; j++) ssum += W3[j + 0];  // placeholder; fixed below
        // recompute properly (avoid misread): row-sum of W3 over output dim
        ssum = 0.f;
#pragma unroll
        for (int j = 0; j < ND; j++) ssum += W3[l*ND + j];
        g_w3s[l] = ssum;
    }
}

// ---------------- split-bf16 warp-MMA GEMM ------------------------------------
// out[b, n] = sum_k X[b,k] * B[n,k]  (B n-major, k contiguous), fp32 via hi/lo split.
enum { TM_L1 = 0, TM_H2 = 1, TM_VU = 2, TM_P = 3, TM_QW = 4 };

template<int TMODE, int KDIM, int LDA, int LDB, int BM>
__global__ void __launch_bounds__(256, 1)
tmma(const float* __restrict__ pX, const float* __restrict__ pB,
     const float* __restrict__ pC, const float* __restrict__ pT,
     const float* __restrict__ w1row) {
    extern __shared__ __align__(1024) char tsm[];
    const uint32_t sb = smem_u32(tsm);
    constexpr int XSZ = BM * 128;          // BM rows x 64 cols x 2B
    constexpr uint32_t OFF_XH = 0, OFF_XL = XSZ;
    constexpr uint32_t OFF_BH = 2 * XSZ, OFF_BL = 2 * XSZ + 8192;
    constexpr int NT = (BM == 128) ? 4 : 2;

    const int tid  = threadIdx.x;
    const int lane = tid & 31, wid = tid >> 5;
    const int zm = blockIdx.z;
    const int n0 = blockIdx.x * 64;
    const int m0 = blockIdx.y * BM;
    const int wm = (BM == 128 ? (wid & 3) : (wid & 1)) * 32;
    const int wn = (BM == 128 ? (wid >> 2) * 32 : (wid >> 1) * 16);

    const float* Xsrc =
        (TMODE == TM_L1) ? pX :
        (TMODE == TM_H2) ? g_h1 :
        (TMODE == TM_VU) ? (zm ? g_h2 : g_h1) :
        (TMODE == TM_P)  ? g_y : g_wb;
    const float* Bsrc =
        (TMODE == TM_L1) ? g_W1T :
        (TMODE == TM_H2) ? g_W2T :
        (TMODE == TM_VU) ? (zm ? g_A : g_AT) : pB;
    float* outp =
        (TMODE == TM_L1) ? g_h1 :
        (TMODE == TM_H2) ? (zm ? g_r2 : g_r1) :
        (TMODE == TM_VU) ? (zm ? g_U : g_V) :
        (TMODE == TM_P)  ? g_wb : g_r1;

    float acc[2][NT][4];
#pragma unroll
    for (int mt = 0; mt < 2; mt++)
#pragma unroll
        for (int nt = 0; nt < NT; nt++)
#pragma unroll
            for (int i = 0; i < 4; i++) acc[mt][nt][i] = 0.f;

    for (int k0 = 0; k0 < KDIM; k0 += 64) {
        // ---- X tile: BM x 64 fp32 -> bf16 hi/lo, SW128 ----
        {
            const int row   = (BM == 128) ? (tid >> 1) : (tid >> 2);
            const int cbase = (BM == 128) ? ((tid & 1) * 32) : ((tid & 3) * 16);
            constexpr int NF4 = (BM == 128) ? 8 : 4;
            const float* xr = Xsrc + (size_t)(m0 + row) * LDA + k0;
#pragma unroll
            for (int i = 0; i < NF4; i++) {
                const int col = cbase + i * 4;
                float4 v = *(const float4*)(xr + col);
                if (TMODE == TM_H2 && zm) {       // d1 = (1-h1^2)*w1t[k]
                    float4 w = *(const float4*)(w1row + k0 + col);
                    v.x = (1.f - v.x*v.x) * w.x; v.y = (1.f - v.y*v.y) * w.y;
                    v.z = (1.f - v.z*v.z) * w.z; v.w = (1.f - v.w*v.w) * w.w;
                } else if (TMODE == TM_VU) {      // a = 1-h^2
                    v.x = 1.f - v.x*v.x; v.y = 1.f - v.y*v.y;
                    v.z = 1.f - v.z*v.z; v.w = 1.f - v.w*v.w;
                }
                uint32_t h01, l01, h23, l23;
                split2(v.x, v.y, h01, l01);
                split2(v.z, v.w, h23, l23);
                uint32_t sw = sw128(row * 128 + col * 2);
                sts_v2(sb + OFF_XH + sw, h01, h23);
                sts_v2(sb + OFF_XL + sw, l01, l23);
            }
        }
        // ---- B tile: 64 x 64 ----
        {
            const int row = tid >> 2;
            const int q   = (tid & 3) * 16;
            const float* br = Bsrc + (size_t)(n0 + row) * LDB + k0;
#pragma unroll
            for (int i = 0; i < 4; i++) {
                const int col = q + i * 4;
                float4 v = *(const float4*)(br + col);
                uint32_t h01, l01, h23, l23;
                split2(v.x, v.y, h01, l01);
                split2(v.z, v.w, h23, l23);
                uint32_t sw = sw128(row * 128 + col * 2);
                sts_v2(sb + OFF_BH + sw, h01, h23);
                sts_v2(sb + OFF_BL + sw, l01, l23);
            }
        }
        __syncthreads();

#pragma unroll
        for (int ks = 0; ks < 4; ks++) {
            uint32_t aH[2][4], aL[2][4];
#pragma unroll
            for (int mt = 0; mt < 2; mt++) {
                uint32_t byte = (uint32_t)(wm + mt * 16 + (lane & 15)) * 128
                              + ks * 32 + (lane >> 4) * 16;
                uint32_t sw = sw128(byte);
                ldsm_x4(aH[mt], sb + OFF_XH + sw);
                ldsm_x4(aL[mt], sb + OFF_XL + sw);
            }
            uint32_t bH[NT][2], bL[NT][2];
#pragma unroll
            for (int nt = 0; nt < NT; nt++) {
                uint32_t byte = (uint32_t)(wn + nt * 8 + (lane & 7)) * 128
                              + ks * 32 + ((lane >> 3) & 1) * 16;
                uint32_t sw = sw128(byte);
                ldsm_x2(bH[nt], sb + OFF_BH + sw);
                ldsm_x2(bL[nt], sb + OFF_BL + sw);
            }
#pragma unroll
            for (int mt = 0; mt < 2; mt++)
#pragma unroll
                for (int nt = 0; nt < NT; nt++) {
                    mma16816(acc[mt][nt], aH[mt], bH[nt]);
                    mma16816(acc[mt][nt], aH[mt], bL[nt]);
                    mma16816(acc[mt][nt], aL[mt], bH[nt]);
                }
        }
        __syncthreads();
    }

    // ---- epilogue ----
#pragma unroll
    for (int mt = 0; mt < 2; mt++)
#pragma unroll
        for (int nt = 0; nt < NT; nt++) {
            const int row = m0 + wm + mt * 16 + (lane >> 2);
            const int col = n0 + wn + nt * 8 + (lane & 3) * 2;
            const float* a = acc[mt][nt];
            size_t i0 = (size_t)row * NH + col;
            size_t i1 = (size_t)(row + 8) * NH + col;
            if constexpr (TMODE == TM_L1) {
                float t0 = pT[row], t1 = pT[row + 8];
                float w0 = w1row[col], w1v = w1row[col + 1];
                float c0 = pC[col],   c1 = pC[col + 1];
                float2 o0 = make_float2(tanhf(a[0] + t0 * w0 + c0),
                                        tanhf(a[1] + t0 * w1v + c1));
                float2 o1 = make_float2(tanhf(a[2] + t1 * w0 + c0),
                                        tanhf(a[3] + t1 * w1v + c1));
                *(float2*)(outp + i0) = o0;
                *(float2*)(outp + i1) = o1;
            } else if constexpr (TMODE == TM_P) {
                float2 h0 = *(const float2*)(g_h2 + i0);
                float2 h1v = *(const float2*)(g_h2 + i1);
                float2 v0 = *(const float2*)(g_V + i0);
                float2 v1 = *(const float2*)(g_V + i1);
                float2 o0 = make_float2(
                    (1.f - h0.x*h0.x) * (a[0] - 2.f*h0.x*v0.x),
                    (1.f - h0.y*h0.y) * (a[1] - 2.f*h0.y*v0.y));
                float2 o1 = make_float2(
                    (1.f - h1v.x*h1v.x) * (a[2] - 2.f*h1v.x*v1.x),
                    (1.f - h1v.y*h1v.y) * (a[3] - 2.f*h1v.y*v1.y));
                *(float2*)(outp + i0) = o0;
                *(float2*)(outp + i1) = o1;
            } else {
                *(float2*)(outp + i0) = make_float2(a[0], a[1]);
                *(float2*)(outp + i1) = make_float2(a[2], a[3]);
            }
        }
}

// ---------------- E1: h2 = tanh(h2raw + b2); s_t = sum d2*w3s -----------------
__global__ void __launch_bounds__(256)
e1_kernel(const float* __restrict__ b2) {
    const int row  = blockIdx.x * 8 + (threadIdx.x >> 5);
    const int lane = threadIdx.x & 31;
    float p = 0.f;
#pragma unroll
    for (int i = 0; i < 16; i++) {
        int c = lane + 32 * i;
        size_t idx = (size_t)row * NH + c;
        float h2 = tanhf(g_r1[idx] + b2[c]);
        g_h2[idx] = h2;
        p += (1.f - h2 * h2) * g_r2[idx] * g_w3s[c];
    }
#pragma unroll
    for (int o = 16; o; o >>= 1) p += __shfl_xor_sync(0xffffffffu, p, o);
    if (lane == 0) g_st[row] = p;
}

// ---------------- thin SIMT GEMMs (N=64 outputs) -------------------------------
enum { M_S = 2, M_LOSS = 6 };

template<int MODE, int KDIM, int LDA, int LDB>
__global__ void __launch_bounds__(256)
gemm_k(const float* __restrict__ pB, const float* __restrict__ pC,
       const float* __restrict__ pD, float* __restrict__ pOut) {
    constexpr int BK = 32;
    __shared__ __align__(16) float Xs[BK][17];
    __shared__ __align__(16) float Bs[BK][68];
    const int tid = threadIdx.x;
    const int tx = tid & 15, ty = tid >> 4;
    const int m0 = blockIdx.y * 16;
    const float* Bg = (MODE == M_S) ? pB : g_W1T;

    float acc[4] = {0.f, 0.f, 0.f, 0.f};
    for (int k0 = 0; k0 < KDIM; k0 += BK) {
        {
            int row = tid >> 4;
            int kc  = (tid & 15) * 2;
            size_t idx = (size_t)(m0 + row) * LDA + k0 + kc;
            if constexpr (MODE == M_S) {
                float2 v = *(const float2*)(g_h2 + idx);
                Xs[kc][row] = v.x; Xs[kc + 1][row] = v.y;
            } else {
                float2 q = *(const float2*)(g_r1 + idx);
                float2 h = *(const float2*)(g_h1 + idx);
                float2 u = *(const float2*)(g_U + idx);
                float a0 = 1.f - h.x * h.x, a1v = 1.f - h.y * h.y;
                Xs[kc][row]     = a0  * q.x - 2.f * h.x * a0  * u.x;
                Xs[kc + 1][row] = a1v * q.y - 2.f * h.y * a1v * u.y;
            }
        }
        {
            int brow = tid >> 4, bnq = (tid & 15) * 4;
            *(float4*)&Bs[brow][bnq] =
                *(const float4*)(Bg + (size_t)(k0 + brow) * LDB + bnq);
            *(float4*)&Bs[brow + 16][bnq] =
                *(const float4*)(Bg + (size_t)(k0 + brow + 16) * LDB + bnq);
        }
        __syncthreads();
#pragma unroll
        for (int kk = 0; kk < BK; kk++) {
            float a = Xs[kk][ty];
            float4 b = *(const float4*)&Bs[kk][tx * 4];
            acc[0] += a * b.x; acc[1] += a * b.y;
            acc[2] += a * b.z; acc[3] += a * b.w;
        }
        __syncthreads();
    }
    const int row = m0 + ty, col = tx * 4;
    if constexpr (MODE == M_S) {
#pragma unroll
        for (int c = 0; c < 4; c++) {
            size_t idx = (size_t)row * ND + col + c;
            float sv = acc[c] + pC[col + c];
            g_s[idx] = sv;
            g_y[idx] = 2.f * sv + pD[idx];
        }
    } else {
        float stv = g_st[row], bet = pC[row];
        float ps = 0.f;
#pragma unroll
        for (int c = 0; c < 4; c++) {
            float g = acc[c] + g_s[(size_t)row * ND + col + c];
            ps += fabsf(stv - 0.5f * bet * g);
        }
#pragma unroll
        for (int o = 8; o; o >>= 1) ps += __shfl_xor_sync(0xffffffffu, ps, o);
        if (tx == 0) pOut[row] = ps * (1.f / 64.f);
    }
}

// ---------------- launch -----------------------------------------------------
#define SM64  (2 * 64 * 128 + 16384)    // 32 KB
#define SM128 (2 * 128 * 128 + 16384)   // 48 KB

extern "C" void kernel_launch(void* const* d_in, const int* in_sizes, int n_in,
                              void* d_out, int out_size) {
    const float* x    = (const float*)d_in[0];
    const float* t    = (const float*)d_in[1];
    const float* beta = (const float*)d_in[2];
    const float* W1   = (const float*)d_in[3];
    const float* b1   = (const float*)d_in[4];
    const float* W2   = (const float*)d_in[5];
    const float* b2   = (const float*)d_in[6];
    const float* W3   = (const float*)d_in[7];
    const float* b3   = (const float*)d_in[8];
    float* out = (float*)d_out;
    const float* w1t = W1 + (size_t)ND * NH;   // W1 row 64 (t-row)

    dim3 gThin(1, NB/16);          // 64 blocks
    dim3 gT128(NH/64, NB/128, 2);  // (8,8,2) = 128 blocks
    dim3 gT64 (NH/64, NB/64,  1);  // (8,16)  = 128 blocks

    prep_kernel<<<dim3(NH/16, NH/16), dim3(16,16)>>>(W1, W2, W3);
    // h1 = tanh([x,t] @ W1 + b1)                     (tensor, K=64 + rank-1)
    tmma<TM_L1, 64, 64, 64, 64><<<gT64, 256, SM64>>>(x, nullptr, b1, t, w1t);
    // h2raw = h1 @ W2 ; z2 = d1 @ W2                 (tensor dual, K=512)
    tmma<TM_H2, NH, NH, NH, 128><<<gT128, 256, SM128>>>(nullptr, nullptr, nullptr, nullptr, w1t);
    // h2 = tanh(h2raw + b2); s_t
    e1_kernel<<<NB/8, 256>>>(b2);
    // V = a1 @ A ; U = a2 @ A^T                      (tensor dual, K=512)
    tmma<TM_VU, NH, NH, NH, 128><<<gT128, 256, SM128>>>(nullptr, nullptr, nullptr, nullptr, w1t);
    // s = h2 @ W3 + b3 ; y = 2s + x                  (thin SIMT)
    gemm_k<M_S, NH, NH, ND><<<gThin, 256>>>(W3, b3, x, nullptr);
    // P = y @ W3^T ; wb = a2*(P - 2 h2 V)            (tensor, K=64)
    tmma<TM_P, 64, 64, 64, 64><<<gT64, 256, SM64>>>(nullptr, W3, nullptr, nullptr, w1t);
    // qw_raw = wb @ W2^T                             (tensor, K=512)
    tmma<TM_QW, NH, NH, NH, 64><<<gT64, 256, SM64>>>(nullptr, W2, nullptr, nullptr, w1t);
    // c on the fly; G = c @ W1x^T + s; loss          (thin SIMT)
    gemm_k<M_LOSS, NH, NH, ND><<<gThin, 256>>>(nullptr, beta, nullptr, out);
}